// round 15
// baseline (speedup 1.0000x reference)
#include <cuda_runtime.h>
#include <cuda_bf16.h>
#include <math.h>
#include <stdint.h>

// ---------------- problem constants ----------------
#define Bb   4
#define Tt   1024
#define Dd   1024
#define Hh   16
#define Ll   2
#define Ee   8
#define DFFc 4096
#define Vv   50257
#define Nn   (Bb*Tt)          // 4096 tokens
#define TOPK 1024
#define HDc  64

typedef __nv_bfloat16  bf16;
typedef __nv_bfloat162 bf162;

// ---------------- scratch (device globals; no allocs allowed) ----------------
__device__ float g_x   [Nn*Dd];          // residual stream
__device__ float g_xn  [Nn*Dd];          // rmsnorm output (fp32, last layer last-pos rows only)
__device__ float g_probsT[Ee*Nn];
__device__ int   g_sel [Ee*TOPK];
__device__ float g_wgt [Ee*TOPK];
__device__ float g_xf  [Bb*Dd];
// last-layer MoE fast path
__device__ int   g_lpk [Ee*Bb];          // >=0 if last-pos token of batch b is in expert e's topk
__device__ float g_lpw [Ee*Bb];          // its routing weight
__device__ float g_hv  [Ee*Bb*DFFc];     // h vectors for active pairs

// bf16 big/small planes (activations)
__device__ bf16 g_xn_b [Nn*Dd],        g_xn_s [Nn*Dd];
__device__ bf16 g_qkv_b[Nn*3*Dd],      g_qkv_s[Nn*3*Dd];
__device__ bf16 g_y_b  [Nn*Dd],        g_y_s  [Nn*Dd];
__device__ bf16 g_h_b  [Ee*TOPK*DFFc], g_h_s  [Ee*TOPK*DFFc];
// bf16 big/small planes (weights, converted once per call)
__device__ bf16 g_attw_b[Ll*3*Dd*Dd],  g_attw_s[Ll*3*Dd*Dd];
__device__ bf16 g_prjw_b[Ll*Dd*Dd],    g_prjw_s[Ll*Dd*Dd];
__device__ bf16 g_fcw_b [Ee*DFFc*Dd],  g_fcw_s [Ee*DFFc*Dd];    // layer 0 only
__device__ bf16 g_mpw_b [Ee*Dd*DFFc],  g_mpw_s [Ee*Dd*DFFc];    // layer 0 only

// ---------------- small helpers ----------------
__device__ __forceinline__ uint32_t smem_u32(const void* p) {
    uint32_t a;
    asm("{ .reg .u64 t; cvta.to.shared.u64 t, %1; cvt.u32.u64 %0, t; }" : "=r"(a) : "l"(p));
    return a;
}
__device__ __forceinline__ void ldsm4(uint32_t* r, uint32_t addr) {
    asm volatile("ldmatrix.sync.aligned.m8n8.x4.shared.b16 {%0,%1,%2,%3}, [%4];"
                 : "=r"(r[0]), "=r"(r[1]), "=r"(r[2]), "=r"(r[3]) : "r"(addr));
}
__device__ __forceinline__ void ldsm4t(uint32_t* r, uint32_t addr) {
    asm volatile("ldmatrix.sync.aligned.m8n8.x4.trans.shared.b16 {%0,%1,%2,%3}, [%4];"
                 : "=r"(r[0]), "=r"(r[1]), "=r"(r[2]), "=r"(r[3]) : "r"(addr));
}
__device__ __forceinline__ void mma_bf16(float* c, const uint32_t* a, uint32_t b0, uint32_t b1) {
    asm volatile(
        "mma.sync.aligned.m16n8k16.row.col.f32.bf16.bf16.f32 "
        "{%0,%1,%2,%3}, {%4,%5,%6,%7}, {%8,%9}, {%0,%1,%2,%3};"
        : "+f"(c[0]), "+f"(c[1]), "+f"(c[2]), "+f"(c[3])
        : "r"(a[0]), "r"(a[1]), "r"(a[2]), "r"(a[3]), "r"(b0), "r"(b1));
}
__device__ __forceinline__ void cpa16(uint32_t s, const void* g) {
    asm volatile("cp.async.cg.shared.global [%0], [%1], 16;" :: "r"(s), "l"(g));
}
__device__ __forceinline__ float gelu_f(float v) {
    return 0.5f * v * (1.f + erff(v * 0.70710678118654752f));
}
__device__ __forceinline__ void split_bf(float v, bf16& b, bf16& s) {
    b = __float2bfloat16(v);
    s = __float2bfloat16(v - __bfloat162float(b));
}
__device__ __forceinline__ uint32_t pack_bf(bf16 lo, bf16 hi) {
    return ((uint32_t)__bfloat16_as_ushort(hi) << 16) | (uint32_t)__bfloat16_as_ushort(lo);
}

// ---------------- weight split conversion (8 floats/thread) ----------------
__global__ void wconvert_kernel(const float* __restrict__ src,
                                bf16* __restrict__ db, bf16* __restrict__ ds, int n) {
    int i = (blockIdx.x * blockDim.x + threadIdx.x) * 8;
    if (i >= n) return;
    float4 v0 = *(const float4*)(src + i);
    float4 v1 = *(const float4*)(src + i + 4);
    bf16 b[8], s[8];
    split_bf(v0.x, b[0], s[0]); split_bf(v0.y, b[1], s[1]);
    split_bf(v0.z, b[2], s[2]); split_bf(v0.w, b[3], s[3]);
    split_bf(v1.x, b[4], s[4]); split_bf(v1.y, b[5], s[5]);
    split_bf(v1.z, b[6], s[6]); split_bf(v1.w, b[7], s[7]);
    uint4 ub, us;
    ub.x = pack_bf(b[0], b[1]); ub.y = pack_bf(b[2], b[3]);
    ub.z = pack_bf(b[4], b[5]); ub.w = pack_bf(b[6], b[7]);
    us.x = pack_bf(s[0], s[1]); us.y = pack_bf(s[2], s[3]);
    us.z = pack_bf(s[4], s[5]); us.w = pack_bf(s[6], s[7]);
    *(uint4*)(db + i) = ub;
    *(uint4*)(ds + i) = us;
}

// ---------------- embedding ----------------
__global__ void embed_kernel(const int* __restrict__ idx,
                             const float* __restrict__ wte,
                             const float* __restrict__ wpe) {
    int n = blockIdx.x;
    int t = n & (Tt - 1);
    int tok = idx[n];
    const float4* src = (const float4*)(wte + (size_t)tok * Dd);
    const float4* pp  = (const float4*)(wpe + (size_t)t * Dd);
    float4* dst = (float4*)(g_x + (size_t)n * Dd);
    int i = threadIdx.x;
    float4 a = src[i], b = pp[i];
    a.x += b.x; a.y += b.y; a.z += b.z; a.w += b.w;
    dst[i] = a;
}

// ---------------- rmsnorm: bf16 planes (+optional fp32 out, +optional fused router) ----------------
// ROUTER=1: warp w computes router logit for expert w from the normalized row
// staged in smem, then thread 0 softmaxes into g_probsT.
// STOREF=1: store fp32 row only for last-position tokens (the only consumers).
template<int ROUTER, int STOREF>
__global__ void rmsnorm_kernel(const float* __restrict__ x,
                               const float* __restrict__ w,
                               float* __restrict__ o,
                               bf16* __restrict__ ob, bf16* __restrict__ os,
                               const float* __restrict__ rw) {
    int n = blockIdx.x;
    const float4* xr = (const float4*)(x + (size_t)n * Dd);
    float4 v = xr[threadIdx.x];
    float s = v.x*v.x + v.y*v.y + v.z*v.z + v.w*v.w;
    __shared__ float red[8];
    for (int off = 16; off; off >>= 1) s += __shfl_xor_sync(~0u, s, off);
    if ((threadIdx.x & 31) == 0) red[threadIdx.x >> 5] = s;
    __syncthreads();
    if (threadIdx.x < 8) {
        float t = red[threadIdx.x];
        for (int off = 4; off; off >>= 1) t += __shfl_xor_sync(0xffu, t, off);
        if (threadIdx.x == 0) red[0] = t;
    }
    __syncthreads();
    float rs = rsqrtf(red[0] * (1.0f / Dd) + 1e-6f);
    float4 wv = ((const float4*)w)[threadIdx.x];
    float4 ov;
    ov.x = v.x * rs * wv.x; ov.y = v.y * rs * wv.y;
    ov.z = v.z * rs * wv.z; ov.w = v.w * rs * wv.w;
    if (STOREF && ((n & (Tt - 1)) == Tt - 1))
        ((float4*)(o + (size_t)n * Dd))[threadIdx.x] = ov;
    bf16 b0,b1,b2,b3,s0,s1,s2,s3;
    split_bf(ov.x,b0,s0); split_bf(ov.y,b1,s1); split_bf(ov.z,b2,s2); split_bf(ov.w,b3,s3);
    bf162* pb = (bf162*)(ob + (size_t)n * Dd) + threadIdx.x * 2;
    bf162* ps = (bf162*)(os + (size_t)n * Dd) + threadIdx.x * 2;
    bf162 t;
    t.x=b0; t.y=b1; pb[0]=t;  t.x=b2; t.y=b3; pb[1]=t;
    t.x=s0; t.y=s1; ps[0]=t;  t.x=s2; t.y=s3; ps[1]=t;

    if (ROUTER) {
        __shared__ float sxn[Dd];
        __shared__ float lg[Ee];
        *(float4*)(sxn + threadIdx.x * 4) = ov;
        __syncthreads();
        int wid = threadIdx.x >> 5, lane = threadIdx.x & 31;   // 8 warps = 8 experts
        const float* we = rw + (size_t)wid * Dd;
        float acc = 0.f;
        for (int i = lane; i < Dd; i += 32) acc += sxn[i] * we[i];
        for (int off = 16; off; off >>= 1) acc += __shfl_xor_sync(~0u, acc, off);
        if (!lane) lg[wid] = acc;
        __syncthreads();
        if (threadIdx.x == 0) {
            float mx = lg[0];
            #pragma unroll
            for (int e = 1; e < Ee; e++) mx = fmaxf(mx, lg[e]);
            float p[Ee]; float sum = 0.f;
            #pragma unroll
            for (int e = 0; e < Ee; e++) { p[e] = expf(lg[e] - mx); sum += p[e]; }
            float inv = 1.f / sum;
            #pragma unroll
            for (int e = 0; e < Ee; e++) g_probsT[(size_t)e * Nn + n] = p[e] * inv;
        }
    }
}

// ---------------- 3xBF16 tensor-core GEMM: C[M,N] = A[M,K] * B[N,K]^T ----------------
// CTA tile 128x256, 8 warps of 64x64 (2x4 grid), BK=32, 3-stage cp.async pipeline.
// acc += Ab*Bb + Ab*Bs + As*Bb, term-major issue.
// OUT: 1=f32 accumulate, 3=bf16 planes (0.125 on cols<Dd), 4=gelu+bf16 planes,
//      5=atomicAdd weighted scatter. GATHER: A rows via sel[].
#define SMSH 40                          // halves per smem row (32 + 8 pad)
#define A_PL (128*SMSH)                  // A plane halves (5120)
#define B_PL (256*SMSH)                  // B plane halves (10240)
#define STG_H (2*A_PL + 2*B_PL)          // halves per stage (30720)
#define STG_B (STG_H*2)                  // bytes per stage (61440)
#define NSTG 3
#define GM_DSM (NSTG*STG_B + 512)        // 184832 B

template<int GATHER, int OUT>
__global__ void __launch_bounds__(256, 1) bf3_gemm(
    const bf16* __restrict__ Ab_, const bf16* __restrict__ As_,
    const bf16* __restrict__ Bb_, const bf16* __restrict__ Bs_,
    float* __restrict__ Cf, bf16* __restrict__ Cb, bf16* __restrict__ Cs,
    const int* __restrict__ sel, const float* __restrict__ wgt,
    int M, int N, int K, long sA, long sB, long sC) {
    extern __shared__ bf16 sh[];
    uint32_t sbase = smem_u32(sh);
    int* srow = (int*)(sh + NSTG * STG_H);

    const int tid = threadIdx.x, lane = tid & 31, warp = tid >> 5;
    const int z = blockIdx.z;
    const int bm = blockIdx.y * 128, bn = blockIdx.x * 256;
    Ab_ += (size_t)z * sA;  As_ += (size_t)z * sA;
    Bb_ += (size_t)z * sB;  Bs_ += (size_t)z * sB;
    const int* selz = sel ? sel + z * TOPK : nullptr;
    const float* wgtz = wgt ? wgt + z * TOPK : nullptr;

    if (GATHER && tid < 128) srow[tid] = selz[bm + tid];
    if (GATHER) __syncthreads();

    auto load_chunk = [&](int kc, int slot) {
        const int ko = kc * 32;
        const uint32_t stg = sbase + slot * STG_B;
        #pragma unroll 2
        for (int i = tid; i < 512; i += 256) {
            int row = i >> 2, c16 = i & 3;
            int gr = GATHER ? srow[row] : (bm + row);
            size_t off = (size_t)gr * K + ko + c16 * 8;
            uint32_t d = stg + (row * SMSH + c16 * 8) * 2;
            cpa16(d, Ab_ + off);
            cpa16(d + A_PL * 2, As_ + off);
        }
        #pragma unroll 4
        for (int i = tid; i < 1024; i += 256) {
            int row = i >> 2, c16 = i & 3;
            size_t off = (size_t)(bn + row) * K + ko + c16 * 8;
            uint32_t d = stg + 2 * A_PL * 2 + (row * SMSH + c16 * 8) * 2;
            cpa16(d, Bb_ + off);
            cpa16(d + B_PL * 2, Bs_ + off);
        }
        asm volatile("cp.async.commit_group;");
    };

    const int wm = warp & 1, wn = warp >> 1;          // 2 x 4 warp grid, 64x64 tiles
    const int arow = (lane & 7) + ((lane >> 3) & 1) * 8;
    const int acol = (lane >> 4) * 8;
    const int brow = (lane & 7) + ((lane >> 4) & 1) * 8;
    const int bcol = ((lane >> 3) & 1) * 8;

    float acc[4][8][4];
    #pragma unroll
    for (int i = 0; i < 4; i++)
        #pragma unroll
        for (int j = 0; j < 8; j++)
            #pragma unroll
            for (int q = 0; q < 4; q++) acc[i][j][q] = 0.f;

    const int NC = K >> 5;
    load_chunk(0, 0);
    load_chunk(1, 1);

    for (int c = 0; c < NC; c++) {
        if (c + 2 < NC) {
            load_chunk(c + 2, (c + 2) % NSTG);
            asm volatile("cp.async.wait_group 2;");
        } else if (c + 1 < NC) {
            asm volatile("cp.async.wait_group 1;");
        } else {
            asm volatile("cp.async.wait_group 0;");
        }
        __syncthreads();

        const uint32_t stg = sbase + (c % NSTG) * STG_B;
        #pragma unroll
        for (int ks = 0; ks < 2; ks++) {
            uint32_t bb[4][4], bs2[4][4], ab[4][4], as2[4][4];
            #pragma unroll
            for (int t16 = 0; t16 < 4; t16++) {
                uint32_t ad = stg + 2 * A_PL * 2 +
                              ((wn * 64 + t16 * 16 + brow) * SMSH + ks * 16 + bcol) * 2;
                ldsm4(bb[t16],  ad);
                ldsm4(bs2[t16], ad + B_PL * 2);
            }
            #pragma unroll
            for (int mf = 0; mf < 4; mf++) {
                uint32_t ad = stg + ((wm * 64 + mf * 16 + arow) * SMSH + ks * 16 + acol) * 2;
                ldsm4(ab[mf],  ad);
                ldsm4(as2[mf], ad + A_PL * 2);
            }
            #pragma unroll
            for (int mf = 0; mf < 4; mf++)
                #pragma unroll
                for (int nf = 0; nf < 8; nf++) {
                    int p = nf >> 1, e = (nf & 1) * 2;
                    mma_bf16(acc[mf][nf], ab[mf], bb[p][e], bb[p][e + 1]);
                }
            #pragma unroll
            for (int mf = 0; mf < 4; mf++)
                #pragma unroll
                for (int nf = 0; nf < 8; nf++) {
                    int p = nf >> 1, e = (nf & 1) * 2;
                    mma_bf16(acc[mf][nf], ab[mf], bs2[p][e], bs2[p][e + 1]);
                }
            #pragma unroll
            for (int mf = 0; mf < 4; mf++)
                #pragma unroll
                for (int nf = 0; nf < 8; nf++) {
                    int p = nf >> 1, e = (nf & 1) * 2;
                    mma_bf16(acc[mf][nf], as2[mf], bb[p][e], bb[p][e + 1]);
                }
        }
        __syncthreads();
    }

    // epilogue
    const int cr = lane >> 2, cc = (lane & 3) * 2;
    #pragma unroll
    for (int mf = 0; mf < 4; mf++) {
        int rk0 = bm + wm * 64 + mf * 16 + cr;
        int tok0 = 0, tok1 = 0; float w0 = 0.f, w1 = 0.f;
        if (OUT == 5) {
            tok0 = selz[rk0]; tok1 = selz[rk0 + 8];
            w0 = wgtz[rk0];   w1 = wgtz[rk0 + 8];
        }
        #pragma unroll
        for (int nf = 0; nf < 8; nf++) {
            int col  = bn + wn * 64 + nf * 8 + cc;
            float c0 = acc[mf][nf][0], c1 = acc[mf][nf][1];
            float c2 = acc[mf][nf][2], c3 = acc[mf][nf][3];
            if (OUT == 4) { c0 = gelu_f(c0); c1 = gelu_f(c1); c2 = gelu_f(c2); c3 = gelu_f(c3); }
            if (OUT == 3) {
                float sc = (col < Dd) ? 0.125f : 1.f;
                c0 *= sc; c1 *= sc; c2 *= sc; c3 *= sc;
            }
            if (OUT == 3 || OUT == 4) {
                size_t o0 = (size_t)z * sC + (size_t)rk0 * N + col;
                size_t o1 = o0 + (size_t)8 * N;
                bf16 b0,b1,b2,b3,s0,s1,s2,s3;
                split_bf(c0,b0,s0); split_bf(c1,b1,s1);
                split_bf(c2,b2,s2); split_bf(c3,b3,s3);
                bf162 t;
                t.x=b0; t.y=b1; *(bf162*)(Cb + o0) = t;
                t.x=b2; t.y=b3; *(bf162*)(Cb + o1) = t;
                t.x=s0; t.y=s1; *(bf162*)(Cs + o0) = t;
                t.x=s2; t.y=s3; *(bf162*)(Cs + o1) = t;
            } else if (OUT == 5) {
                float* d0 = Cf + (size_t)tok0 * N + col;
                float* d1 = Cf + (size_t)tok1 * N + col;
                atomicAdd(d0,     w0 * c0); atomicAdd(d0 + 1, w0 * c1);
                atomicAdd(d1,     w1 * c2); atomicAdd(d1 + 1, w1 * c3);
            } else {
                float* p0 = Cf + (size_t)z * sC + (size_t)rk0 * N + col;
                float* p1 = p0 + (size_t)8 * N;
                p0[0] += c0; p0[1] += c1;
                p1[0] += c2; p1[1] += c3;
            }
        }
    }
}

// ---------------- tensor-core flash attention (causal, HD=64, BQ=BK=64) ----------------
// 4 warps, each owns 16 Q rows. 3xBF16 split; K/V double-buffered; 2 CTAs/SM.
// LPT: heaviest q-tiles (largest qt) are launched first.
#define FH 72                       // smem stride in halves
#define FPL (64*FH*2)               // plane bytes (9216)
#define FS2 (10*FPL)                // Q(2) + 2 stages of K/V(4 each) = 92160
__global__ void __launch_bounds__(128, 2) flashm_kernel() {
    extern __shared__ bf16 fsh[];
    uint32_t sb = smem_u32(fsh);
    int qt = (Tt / 64 - 1) - blockIdx.x;       // reverse order: heavy tiles first
    int bh = blockIdx.y;
    int b = bh >> 4, h = bh & 15;
    int tid = threadIdx.x, lane = tid & 31, warp = tid >> 5;

    for (int i = tid; i < 512; i += 128) {
        int row = i >> 3, cc = i & 7;
        size_t g = ((size_t)(b * Tt + qt * 64 + row)) * (3 * Dd) + h * HDc + cc * 8;
        uint32_t ds = (row * FH + cc * 8) * 2;
        cpa16(sb + ds,       g_qkv_b + g);
        cpa16(sb + FPL + ds, g_qkv_s + g);
    }
    asm volatile("cp.async.commit_group;");

    auto load_kv = [&](int kt, int s) {
        uint32_t base = sb + (2 + 4 * s) * FPL;
        for (int i = tid; i < 512; i += 128) {
            int row = i >> 3, cc = i & 7;
            size_t gk = ((size_t)(b * Tt + kt * 64 + row)) * (3 * Dd) + Dd + h * HDc + cc * 8;
            size_t gv = gk + Dd;
            uint32_t ds = (row * FH + cc * 8) * 2;
            cpa16(base + ds,           g_qkv_b + gk);
            cpa16(base + FPL + ds,     g_qkv_s + gk);
            cpa16(base + 2 * FPL + ds, g_qkv_b + gv);
            cpa16(base + 3 * FPL + ds, g_qkv_s + gv);
        }
        asm volatile("cp.async.commit_group;");
    };

    load_kv(0, 0);
    asm volatile("cp.async.wait_group 1;");
    __syncthreads();

    uint32_t qb[4][4], qs[4][4];
    {
        int row = warp * 16 + (lane & 15);
        #pragma unroll
        for (int kc = 0; kc < 4; kc++) {
            int col = kc * 16 + (lane >> 4) * 8;
            uint32_t ad = (row * FH + col) * 2;
            ldsm4(qb[kc], sb + ad);
            ldsm4(qs[kc], sb + FPL + ad);
        }
    }

    float Oacc[8][4];
    #pragma unroll
    for (int i = 0; i < 8; i++)
        #pragma unroll
        for (int q = 0; q < 4; q++) Oacc[i][q] = 0.f;
    float mrun[2] = {-1e30f, -1e30f}, lrun[2] = {0.f, 0.f};

    const int qrowA = qt * 64 + warp * 16 + (lane >> 2);

    for (int kt = 0; kt <= qt; kt++) {
        if (kt + 1 <= qt) {
            load_kv(kt + 1, (kt + 1) & 1);
            asm volatile("cp.async.wait_group 1;");
        } else {
            asm volatile("cp.async.wait_group 0;");
        }
        __syncthreads();
        uint32_t kvb = sb + (2 + 4 * (kt & 1)) * FPL;

        float S[8][4];
        #pragma unroll
        for (int i = 0; i < 8; i++)
            #pragma unroll
            for (int q = 0; q < 4; q++) S[i][q] = 0.f;
        #pragma unroll
        for (int kc = 0; kc < 4; kc++) {
            int c = kc * 16 + (lane >> 4) * 8;
            #pragma unroll
            for (int g2 = 0; g2 < 4; g2++) {
                uint32_t kbF[4], ksF[4];
                uint32_t ad = ((g2 * 16 + (lane & 15)) * FH + c) * 2;
                ldsm4(kbF, kvb + ad);
                ldsm4(ksF, kvb + FPL + ad);
                mma_bf16(S[2*g2],   qb[kc], kbF[0], kbF[2]);
                mma_bf16(S[2*g2+1], qb[kc], kbF[1], kbF[3]);
                mma_bf16(S[2*g2],   qb[kc], ksF[0], ksF[2]);
                mma_bf16(S[2*g2+1], qb[kc], ksF[1], ksF[3]);
                mma_bf16(S[2*g2],   qs[kc], kbF[0], kbF[2]);
                mma_bf16(S[2*g2+1], qs[kc], kbF[1], kbF[3]);
            }
        }

        if (kt == qt) {
            #pragma unroll
            for (int nt = 0; nt < 8; nt++) {
                int t0 = kt * 64 + nt * 8 + (lane & 3) * 2;
                if (t0     > qrowA)     S[nt][0] = -1e30f;
                if (t0 + 1 > qrowA)     S[nt][1] = -1e30f;
                if (t0     > qrowA + 8) S[nt][2] = -1e30f;
                if (t0 + 1 > qrowA + 8) S[nt][3] = -1e30f;
            }
        }

        float mA = -1e30f, mB = -1e30f;
        #pragma unroll
        for (int nt = 0; nt < 8; nt++) {
            mA = fmaxf(mA, fmaxf(S[nt][0], S[nt][1]));
            mB = fmaxf(mB, fmaxf(S[nt][2], S[nt][3]));
        }
        mA = fmaxf(mA, __shfl_xor_sync(~0u, mA, 1));
        mA = fmaxf(mA, __shfl_xor_sync(~0u, mA, 2));
        mB = fmaxf(mB, __shfl_xor_sync(~0u, mB, 1));
        mB = fmaxf(mB, __shfl_xor_sync(~0u, mB, 2));
        float mnA = fmaxf(mrun[0], mA), mnB = fmaxf(mrun[1], mB);
        float aA = expf(mrun[0] - mnA), aB = expf(mrun[1] - mnB);
        float sumA = 0.f, sumB = 0.f;
        uint32_t Pb[4][4], Ps[4][4];
        #pragma unroll
        for (int tc = 0; tc < 4; tc++) {
            #pragma unroll
            for (int hf = 0; hf < 2; hf++) {
                int nt = tc * 2 + hf;
                float p0 = expf(S[nt][0] - mnA), p1 = expf(S[nt][1] - mnA);
                float p2 = expf(S[nt][2] - mnB), p3 = expf(S[nt][3] - mnB);
                sumA += p0 + p1; sumB += p2 + p3;
                bf16 b0,b1,b2,b3,s0,s1,s2,s3;
                split_bf(p0,b0,s0); split_bf(p1,b1,s1);
                split_bf(p2,b2,s2); split_bf(p3,b3,s3);
                Pb[tc][hf*2+0] = pack_bf(b0, b1);
                Pb[tc][hf*2+1] = pack_bf(b2, b3);
                Ps[tc][hf*2+0] = pack_bf(s0, s1);
                Ps[tc][hf*2+1] = pack_bf(s2, s3);
            }
        }
        sumA += __shfl_xor_sync(~0u, sumA, 1);
        sumA += __shfl_xor_sync(~0u, sumA, 2);
        sumB += __shfl_xor_sync(~0u, sumB, 1);
        sumB += __shfl_xor_sync(~0u, sumB, 2);
        lrun[0] = lrun[0] * aA + sumA;  mrun[0] = mnA;
        lrun[1] = lrun[1] * aB + sumB;  mrun[1] = mnB;
        #pragma unroll
        for (int nt = 0; nt < 8; nt++) {
            Oacc[nt][0] *= aA; Oacc[nt][1] *= aA;
            Oacc[nt][2] *= aB; Oacc[nt][3] *= aB;
        }

        #pragma unroll
        for (int tc = 0; tc < 4; tc++) {
            int r = tc * 16 + (lane & 15);
            #pragma unroll
            for (int dg = 0; dg < 4; dg++) {
                int c = dg * 16 + (lane >> 4) * 8;
                uint32_t vbF[4], vsF[4];
                uint32_t ad = (r * FH + c) * 2;
                ldsm4t(vbF, kvb + 2 * FPL + ad);
                ldsm4t(vsF, kvb + 3 * FPL + ad);
                mma_bf16(Oacc[2*dg],   Pb[tc], vbF[0], vbF[1]);
                mma_bf16(Oacc[2*dg+1], Pb[tc], vbF[2], vbF[3]);
                mma_bf16(Oacc[2*dg],   Pb[tc], vsF[0], vsF[1]);
                mma_bf16(Oacc[2*dg+1], Pb[tc], vsF[2], vsF[3]);
                mma_bf16(Oacc[2*dg],   Ps[tc], vbF[0], vbF[1]);
                mma_bf16(Oacc[2*dg+1], Ps[tc], vbF[2], vbF[3]);
            }
        }
        __syncthreads();
    }

    float liA = 1.f / lrun[0], liB = 1.f / lrun[1];
    size_t rowA = (size_t)(b * Tt + qt * 64 + warp * 16 + (lane >> 2)) * Dd;
    size_t rowB = rowA + (size_t)8 * Dd;
    #pragma unroll
    for (int nt = 0; nt < 8; nt++) {
        int col = h * HDc + nt * 8 + (lane & 3) * 2;
        float v0 = Oacc[nt][0] * liA, v1 = Oacc[nt][1] * liA;
        float v2 = Oacc[nt][2] * liB, v3 = Oacc[nt][3] * liB;
        bf16 b0,b1,b2,b3,s0,s1,s2,s3;
        split_bf(v0,b0,s0); split_bf(v1,b1,s1);
        split_bf(v2,b2,s2); split_bf(v3,b3,s3);
        bf162 t;
        t.x=b0; t.y=b1; *(bf162*)(g_y_b + rowA + col) = t;
        t.x=b2; t.y=b3; *(bf162*)(g_y_b + rowB + col) = t;
        t.x=s0; t.y=s1; *(bf162*)(g_y_s + rowA + col) = t;
        t.x=s2; t.y=s3; *(bf162*)(g_y_s + rowB + col) = t;
    }
}

// ---------------- per-expert top-1024 of 4096 via in-smem bitonic sort ----------------
__global__ void __launch_bounds__(1024) topk_kernel() {
    int e = blockIdx.x;
    __shared__ float key[4096];
    __shared__ int   val[4096];
    for (int i = threadIdx.x; i < 4096; i += 1024) {
        key[i] = g_probsT[(size_t)e * Nn + i];
        val[i] = i;
    }
    __syncthreads();
    for (int k = 2; k <= 4096; k <<= 1) {
        for (int j = k >> 1; j > 0; j >>= 1) {
            for (int i = threadIdx.x; i < 4096; i += 1024) {
                int ixj = i ^ j;
                if (ixj > i) {
                    bool dirDesc = ((i & k) == 0);
                    float ka = key[i], kb = key[ixj];
                    int va = val[i], vb = val[ixj];
                    bool aFirst = (ka > kb) || (ka == kb && va < vb);
                    if (dirDesc ? !aFirst : aFirst) {
                        key[i] = kb; key[ixj] = ka;
                        val[i] = vb; val[ixj] = va;
                    }
                }
            }
            __syncthreads();
        }
    }
    if (threadIdx.x < TOPK) {
        g_sel[e * TOPK + threadIdx.x] = val[threadIdx.x];
        g_wgt[e * TOPK + threadIdx.x] = key[threadIdx.x];
    }
}

// ---------------- last-layer MoE fast path ----------------
// rank-count: last-pos token of batch b is in expert e's top-1024 iff
// #{t: p[t] > p[target]} + #{t < target: p[t] == p[target]} < TOPK.
__global__ void __launch_bounds__(1024) moe_rank_kernel() {
    int e = blockIdx.x >> 2, b = blockIdx.x & 3;
    int target = b * Tt + (Tt - 1);
    const float* pr = g_probsT + (size_t)e * Nn;
    float pt = pr[target];
    int cnt = 0;
    for (int i = threadIdx.x; i < Nn; i += 1024) {
        float v = pr[i];
        if (v > pt || (v == pt && i < target)) cnt++;
    }
    for (int off = 16; off; off >>= 1) cnt += __shfl_xor_sync(~0u, cnt, off);
    __shared__ int red[32];
    if ((threadIdx.x & 31) == 0) red[threadIdx.x >> 5] = cnt;
    __syncthreads();
    if (threadIdx.x < 32) {
        int t = red[threadIdx.x];
        for (int off = 16; off; off >>= 1) t += __shfl_xor_sync(~0u, t, off);
        if (threadIdx.x == 0) {
            g_lpk[blockIdx.x] = (t < TOPK) ? 0 : -1;
            g_lpw[blockIdx.x] = pt;
        }
    }
}

__global__ void __launch_bounds__(256) moe_fcvec_kernel(const float* __restrict__ fcw) {
    int e = blockIdx.x;
    __shared__ float sx[Bb][Dd];
    __shared__ int act[Bb];
    if (threadIdx.x < Bb) act[threadIdx.x] = g_lpk[e * Bb + threadIdx.x];
    __syncthreads();
    if (act[0] < 0 && act[1] < 0 && act[2] < 0 && act[3] < 0) return;
    #pragma unroll
    for (int b = 0; b < Bb; b++) {
        const float* xr = g_xn + ((size_t)(b * Tt + Tt - 1)) * Dd;
        for (int i = threadIdx.x; i < Dd; i += 256)
            sx[b][i] = (act[b] >= 0) ? xr[i] : 0.f;
    }
    __syncthreads();
    int warp = threadIdx.x >> 5, lane = threadIdx.x & 31;
    for (int j = 0; j < 32; j++) {
        int f = blockIdx.y * 256 + warp * 32 + j;
        const float* wr = fcw + ((size_t)e * DFFc + f) * Dd;
        float a0 = 0.f, a1 = 0.f, a2 = 0.f, a3 = 0.f;
        for (int i = lane; i < Dd; i += 32) {
            float wv = wr[i];
            a0 += wv * sx[0][i]; a1 += wv * sx[1][i];
            a2 += wv * sx[2][i]; a3 += wv * sx[3][i];
        }
        for (int off = 16; off; off >>= 1) {
            a0 += __shfl_xor_sync(~0u, a0, off);
            a1 += __shfl_xor_sync(~0u, a1, off);
            a2 += __shfl_xor_sync(~0u, a2, off);
            a3 += __shfl_xor_sync(~0u, a3, off);
        }
        if (!lane) {
            if (act[0] >= 0) g_hv[((size_t)e * Bb + 0) * DFFc + f] = gelu_f(a0);
            if (act[1] >= 0) g_hv[((size_t)e * Bb + 1) * DFFc + f] = gelu_f(a1);
            if (act[2] >= 0) g_hv[((size_t)e * Bb + 2) * DFFc + f] = gelu_f(a2);
            if (act[3] >= 0) g_hv[((size_t)e * Bb + 3) * DFFc + f] = gelu_f(a3);
        }
    }
}

__global__ void __launch_bounds__(256) moe_mpvec_kernel(const float* __restrict__ mpw) {
    extern __shared__ float shv[];
    int e = blockIdx.x;
    __shared__ int act[Bb];
    __shared__ float awt[Bb];
    if (threadIdx.x < Bb) {
        act[threadIdx.x] = g_lpk[e * Bb + threadIdx.x];
        awt[threadIdx.x] = g_lpw[e * Bb + threadIdx.x];
    }
    __syncthreads();
    if (act[0] < 0 && act[1] < 0 && act[2] < 0 && act[3] < 0) return;
    #pragma unroll
    for (int b = 0; b < Bb; b++) {
        const float* hr = g_hv + ((size_t)e * Bb + b) * DFFc;
        for (int i = threadIdx.x; i < DFFc; i += 256)
            shv[b * DFFc + i] = (act[b] >= 0) ? hr[i] : 0.f;
    }
    __syncthreads();
    int warp = threadIdx.x >> 5, lane = threadIdx.x & 31;
    for (int j = 0; j < 32; j++) {
        int d = blockIdx.y * 256 + warp * 32 + j;
        const float* wr = mpw + ((size_t)e * Dd + d) * DFFc;
        float a0 = 0.f, a1 = 0.f, a2 = 0.f, a3 = 0.f;
        for (int i = lane; i < DFFc; i += 32) {
            float wv = wr[i];
            a0 += wv * shv[i]; a1 += wv * shv[DFFc + i];
            a2 += wv * shv[2 * DFFc + i]; a3 += wv * shv[3 * DFFc + i];
        }
        for (int off = 16; off; off >>= 1) {
            a0 += __shfl_xor_sync(~0u, a0, off);
            a1 += __shfl_xor_sync(~0u, a1, off);
            a2 += __shfl_xor_sync(~0u, a2, off);
            a3 += __shfl_xor_sync(~0u, a3, off);
        }
        if (!lane) {
            if (act[0] >= 0) atomicAdd(&g_x[((size_t)(0 * Tt + Tt - 1)) * Dd + d], awt[0] * a0);
            if (act[1] >= 0) atomicAdd(&g_x[((size_t)(1 * Tt + Tt - 1)) * Dd + d], awt[1] * a1);
            if (act[2] >= 0) atomicAdd(&g_x[((size_t)(2 * Tt + Tt - 1)) * Dd + d], awt[2] * a2);
            if (act[3] >= 0) atomicAdd(&g_x[((size_t)(3 * Tt + Tt - 1)) * Dd + d], awt[3] * a3);
        }
    }
}

// ---------------- final rmsnorm (last position of each batch only) ----------------
__global__ void lnf_kernel(const float* __restrict__ w) {
    int b = blockIdx.x;
    const float4* xr = (const float4*)(g_x + ((size_t)b * Tt + (Tt - 1)) * Dd);
    float4 v = xr[threadIdx.x];
    float s = v.x*v.x + v.y*v.y + v.z*v.z + v.w*v.w;
    __shared__ float red[8];
    for (int off = 16; off; off >>= 1) s += __shfl_xor_sync(~0u, s, off);
    if ((threadIdx.x & 31) == 0) red[threadIdx.x >> 5] = s;
    __syncthreads();
    if (threadIdx.x < 8) {
        float t = red[threadIdx.x];
        for (int off = 4; off; off >>= 1) t += __shfl_xor_sync(0xffu, t, off);
        if (threadIdx.x == 0) red[0] = t;
    }
    __syncthreads();
    float rs = rsqrtf(red[0] * (1.0f / Dd) + 1e-6f);
    float4 wv = ((const float4*)w)[threadIdx.x];
    float4 ov;
    ov.x = v.x * rs * wv.x; ov.y = v.y * rs * wv.y;
    ov.z = v.z * rs * wv.z; ov.w = v.w * rs * wv.w;
    ((float4*)(g_xf + (size_t)b * Dd))[threadIdx.x] = ov;
}

// ---------------- LM head: logits[b][v] = dot(xf[b], wte[v]) ----------------
__global__ void __launch_bounds__(256) lmhead_kernel(const float* __restrict__ wte,
                                                     float* __restrict__ out) {
    __shared__ float4 sx[4 * 256];
    for (int i = threadIdx.x; i < 1024; i += 256) sx[i] = ((const float4*)g_xf)[i];
    __syncthreads();
    int w = threadIdx.x >> 5, lane = threadIdx.x & 31;
    int v = blockIdx.x * 8 + w;
    if (v >= Vv) return;
    const float4* wr = (const float4*)(wte + (size_t)v * Dd);
    float a0 = 0.f, a1 = 0.f, a2 = 0.f, a3 = 0.f;
    for (int i = lane; i < 256; i += 32) {
        float4 t = wr[i];
        float4 x0 = sx[i], x1 = sx[256 + i], x2 = sx[512 + i], x3 = sx[768 + i];
        a0 += t.x*x0.x + t.y*x0.y + t.z*x0.z + t.w*x0.w;
        a1 += t.x*x1.x + t.y*x1.y + t.z*x1.z + t.w*x1.w;
        a2 += t.x*x2.x + t.y*x2.y + t.z*x2.z + t.w*x2.w;
        a3 += t.x*x3.x + t.y*x3.y + t.z*x3.z + t.w*x3.w;
    }
    for (int off = 16; off; off >>= 1) {
        a0 += __shfl_xor_sync(~0u, a0, off);
        a1 += __shfl_xor_sync(~0u, a1, off);
        a2 += __shfl_xor_sync(~0u, a2, off);
        a3 += __shfl_xor_sync(~0u, a3, off);
    }
    if (!lane) {
        out[v]          = a0;
        out[Vv + v]     = a1;
        out[2 * Vv + v] = a2;
        out[3 * Vv + v] = a3;
    }
}

// ---------------- host orchestration ----------------
extern "C" void kernel_launch(void* const* d_in, const int* in_sizes, int n_in,
                              void* d_out, int out_size) {
    const int*   idx  = (const int*)  d_in[0];
    const float* wte  = (const float*)d_in[1];
    const float* wpe  = (const float*)d_in[2];
    const float* ln1  = (const float*)d_in[3];
    const float* attw = (const float*)d_in[4];
    const float* prjw = (const float*)d_in[5];
    const float* ln2  = (const float*)d_in[6];
    const float* rw   = (const float*)d_in[7];
    const float* fcw  = (const float*)d_in[8];
    const float* mpw  = (const float*)d_in[9];
    const float* lnf  = (const float*)d_in[10];
    float* out = (float*)d_out;

    void* p;
    cudaGetSymbolAddress(&p, g_x);     float* x    = (float*)p;
    cudaGetSymbolAddress(&p, g_xn);    float* xn   = (float*)p;
    cudaGetSymbolAddress(&p, g_sel);   int*   sel  = (int*)p;
    cudaGetSymbolAddress(&p, g_wgt);   float* wgt  = (float*)p;
    cudaGetSymbolAddress(&p, g_xn_b);  bf16* xn_b  = (bf16*)p;
    cudaGetSymbolAddress(&p, g_xn_s);  bf16* xn_s  = (bf16*)p;
    cudaGetSymbolAddress(&p, g_qkv_b); bf16* qkv_b = (bf16*)p;
    cudaGetSymbolAddress(&p, g_qkv_s); bf16* qkv_s = (bf16*)p;
    cudaGetSymbolAddress(&p, g_y_b);   bf16* y_b   = (bf16*)p;
    cudaGetSymbolAddress(&p, g_y_s);   bf16* y_s   = (bf16*)p;
    cudaGetSymbolAddress(&p, g_h_b);   bf16* h_b   = (bf16*)p;
    cudaGetSymbolAddress(&p, g_h_s);   bf16* h_s   = (bf16*)p;
    cudaGetSymbolAddress(&p, g_attw_b);bf16* attw_b= (bf16*)p;
    cudaGetSymbolAddress(&p, g_attw_s);bf16* attw_s= (bf16*)p;
    cudaGetSymbolAddress(&p, g_prjw_b);bf16* prjw_b= (bf16*)p;
    cudaGetSymbolAddress(&p, g_prjw_s);bf16* prjw_s= (bf16*)p;
    cudaGetSymbolAddress(&p, g_fcw_b); bf16* fcw_b = (bf16*)p;
    cudaGetSymbolAddress(&p, g_fcw_s); bf16* fcw_s = (bf16*)p;
    cudaGetSymbolAddress(&p, g_mpw_b); bf16* mpw_b = (bf16*)p;
    cudaGetSymbolAddress(&p, g_mpw_s); bf16* mpw_s = (bf16*)p;

    cudaFuncSetAttribute(flashm_kernel, cudaFuncAttributeMaxDynamicSharedMemorySize, FS2);
    cudaFuncSetAttribute(bf3_gemm<0,3>, cudaFuncAttributeMaxDynamicSharedMemorySize, GM_DSM);
    cudaFuncSetAttribute(bf3_gemm<0,1>, cudaFuncAttributeMaxDynamicSharedMemorySize, GM_DSM);
    cudaFuncSetAttribute(bf3_gemm<1,4>, cudaFuncAttributeMaxDynamicSharedMemorySize, GM_DSM);
    cudaFuncSetAttribute(bf3_gemm<0,5>, cudaFuncAttributeMaxDynamicSharedMemorySize, GM_DSM);
    cudaFuncSetAttribute(moe_mpvec_kernel, cudaFuncAttributeMaxDynamicSharedMemorySize, Bb * DFFc * 4);

    // weight split conversion (once per call); fc/mp only needed for layer 0
    wconvert_kernel<<<(Ll*3*Dd*Dd)/2048, 256>>>(attw, attw_b, attw_s, Ll*3*Dd*Dd);
    wconvert_kernel<<<(Ll*Dd*Dd)/2048, 256>>>(prjw, prjw_b, prjw_s, Ll*Dd*Dd);
    wconvert_kernel<<<(Ee*DFFc*Dd)/2048, 256>>>(fcw, fcw_b, fcw_s, Ee*DFFc*Dd);
    wconvert_kernel<<<(Ee*Dd*DFFc)/2048, 256>>>(mpw, mpw_b, mpw_s, Ee*Dd*DFFc);

    embed_kernel<<<Nn, 256>>>(idx, wte, wpe);

    for (int l = 0; l < Ll; l++) {
        // attention block
        rmsnorm_kernel<0,0><<<Nn, 256>>>(x, ln1 + (size_t)l * Dd, nullptr, xn_b, xn_s, nullptr);
        bf3_gemm<0,3><<<dim3(3*Dd/256, Nn/128, 1), 256, GM_DSM>>>(
            xn_b, xn_s,
            attw_b + (size_t)l * 3 * Dd * Dd, attw_s + (size_t)l * 3 * Dd * Dd,
            nullptr, qkv_b, qkv_s, nullptr, nullptr,
            Nn, 3*Dd, Dd, 0, 0, 0);
        flashm_kernel<<<dim3(Tt/64, Bb*Hh), 128, FS2>>>();
        bf3_gemm<0,1><<<dim3(Dd/256, Nn/128, 1), 256, GM_DSM>>>(
            y_b, y_s,
            prjw_b + (size_t)l * Dd * Dd, prjw_s + (size_t)l * Dd * Dd,
            x, nullptr, nullptr, nullptr, nullptr,
            Nn, Dd, Dd, 0, 0, 0);                       // x += proj(y)

        // MoE block (router fused into rmsnorm2)
        if (l < Ll - 1) {
            rmsnorm_kernel<1,0><<<Nn, 256>>>(x, ln2 + (size_t)l * Dd, nullptr, xn_b, xn_s,
                                             rw + (size_t)l * Ee * Dd);
            topk_kernel<<<Ee, 1024>>>();
            bf3_gemm<1,4><<<dim3(DFFc/256, TOPK/128, Ee), 256, GM_DSM>>>(
                xn_b, xn_s,
                fcw_b, fcw_s,
                nullptr, h_b, h_s, sel, wgt,
                TOPK, DFFc, Dd,
                0, (long)DFFc * Dd, (long)TOPK * DFFc);
            bf3_gemm<0,5><<<dim3(Dd/256, TOPK/128, Ee), 256, GM_DSM>>>(
                h_b, h_s,
                mpw_b, mpw_s,
                x, nullptr, nullptr, sel, wgt,
                TOPK, Dd, DFFc,
                (long)TOPK * DFFc, (long)Dd * DFFc, 0); // x += w * expert_out (atomic)
        } else {
            // last layer: only the 4 last-position tokens affect the output.
            rmsnorm_kernel<1,1><<<Nn, 256>>>(x, ln2 + (size_t)l * Dd, xn, xn_b, xn_s,
                                             rw + (size_t)l * Ee * Dd);
            moe_rank_kernel<<<Ee * Bb, 1024>>>();
            moe_fcvec_kernel<<<dim3(Ee, DFFc/256), 256>>>(fcw + (size_t)l * Ee * DFFc * Dd);
            moe_mpvec_kernel<<<dim3(Ee, Dd/256), 256, Bb * DFFc * 4>>>(mpw + (size_t)l * Ee * Dd * DFFc);
        }
    }

    lnf_kernel<<<Bb, 256>>>(lnf);
    lmhead_kernel<<<(Vv + 7) / 8, 256>>>(wte, out);
}

// round 17
// speedup vs baseline: 1.4824x; 1.4824x over previous
#include <cuda_runtime.h>
#include <cuda_bf16.h>
#include <math.h>
#include <stdint.h>

// ---------------- problem constants ----------------
#define Bb   4
#define Tt   1024
#define Dd   1024
#define Hh   16
#define Ll   2
#define Ee   8
#define DFFc 4096
#define Vv   50257
#define Nn   (Bb*Tt)          // 4096 tokens
#define TOPK 1024
#define HDc  64

typedef __nv_bfloat16  bf16;
typedef __nv_bfloat162 bf162;

// ---------------- scratch (device globals; no allocs allowed) ----------------
__device__ float g_x   [Nn*Dd];          // residual stream
__device__ float g_xn  [Nn*Dd];          // rmsnorm output (fp32, last layer last-pos rows only)
__device__ float g_probsT[Ee*Nn];
__device__ int   g_sel [Ee*TOPK];
__device__ float g_wgt [Ee*TOPK];
__device__ float g_xf  [Bb*Dd];
// last-layer MoE fast path
__device__ int   g_lpk [Ee*Bb];          // >=0 if last-pos token of batch b is in expert e's topk
__device__ float g_lpw [Ee*Bb];          // its routing weight
__device__ float g_hv  [Ee*Bb*DFFc];     // h vectors for active pairs

// bf16 big/small planes (activations)
__device__ bf16 g_xn_b [Nn*Dd],        g_xn_s [Nn*Dd];
__device__ bf16 g_qkv_b[Nn*3*Dd],      g_qkv_s[Nn*3*Dd];
__device__ bf16 g_y_b  [Nn*Dd],        g_y_s  [Nn*Dd];
__device__ bf16 g_h_b  [Ee*TOPK*DFFc], g_h_s  [Ee*TOPK*DFFc];
// bf16 big/small planes (weights, converted once per call)
__device__ bf16 g_attw_b[Ll*3*Dd*Dd],  g_attw_s[Ll*3*Dd*Dd];
__device__ bf16 g_prjw_b[Ll*Dd*Dd],    g_prjw_s[Ll*Dd*Dd];
__device__ bf16 g_fcw_b [Ee*DFFc*Dd],  g_fcw_s [Ee*DFFc*Dd];    // layer 0 only
__device__ bf16 g_mpw_b [Ee*Dd*DFFc],  g_mpw_s [Ee*Dd*DFFc];    // layer 0 only

// ---------------- small helpers ----------------
__device__ __forceinline__ uint32_t smem_u32(const void* p) {
    uint32_t a;
    asm("{ .reg .u64 t; cvta.to.shared.u64 t, %1; cvt.u32.u64 %0, t; }" : "=r"(a) : "l"(p));
    return a;
}
__device__ __forceinline__ void ldsm4(uint32_t* r, uint32_t addr) {
    asm volatile("ldmatrix.sync.aligned.m8n8.x4.shared.b16 {%0,%1,%2,%3}, [%4];"
                 : "=r"(r[0]), "=r"(r[1]), "=r"(r[2]), "=r"(r[3]) : "r"(addr));
}
__device__ __forceinline__ void ldsm4t(uint32_t* r, uint32_t addr) {
    asm volatile("ldmatrix.sync.aligned.m8n8.x4.trans.shared.b16 {%0,%1,%2,%3}, [%4];"
                 : "=r"(r[0]), "=r"(r[1]), "=r"(r[2]), "=r"(r[3]) : "r"(addr));
}
__device__ __forceinline__ void mma_bf16(float* c, const uint32_t* a, uint32_t b0, uint32_t b1) {
    asm volatile(
        "mma.sync.aligned.m16n8k16.row.col.f32.bf16.bf16.f32 "
        "{%0,%1,%2,%3}, {%4,%5,%6,%7}, {%8,%9}, {%0,%1,%2,%3};"
        : "+f"(c[0]), "+f"(c[1]), "+f"(c[2]), "+f"(c[3])
        : "r"(a[0]), "r"(a[1]), "r"(a[2]), "r"(a[3]), "r"(b0), "r"(b1));
}
__device__ __forceinline__ void cpa16(uint32_t s, const void* g) {
    asm volatile("cp.async.cg.shared.global [%0], [%1], 16;" :: "r"(s), "l"(g));
}
__device__ __forceinline__ float gelu_f(float v) {
    return 0.5f * v * (1.f + erff(v * 0.70710678118654752f));
}
__device__ __forceinline__ void split_bf(float v, bf16& b, bf16& s) {
    b = __float2bfloat16(v);
    s = __float2bfloat16(v - __bfloat162float(b));
}
__device__ __forceinline__ uint32_t pack_bf(bf16 lo, bf16 hi) {
    return ((uint32_t)__bfloat16_as_ushort(hi) << 16) | (uint32_t)__bfloat16_as_ushort(lo);
}

// ---------------- weight split conversion (8 floats/thread) ----------------
__global__ void wconvert_kernel(const float* __restrict__ src,
                                bf16* __restrict__ db, bf16* __restrict__ ds, int n) {
    int i = (blockIdx.x * blockDim.x + threadIdx.x) * 8;
    if (i >= n) return;
    float4 v0 = *(const float4*)(src + i);
    float4 v1 = *(const float4*)(src + i + 4);
    bf16 b[8], s[8];
    split_bf(v0.x, b[0], s[0]); split_bf(v0.y, b[1], s[1]);
    split_bf(v0.z, b[2], s[2]); split_bf(v0.w, b[3], s[3]);
    split_bf(v1.x, b[4], s[4]); split_bf(v1.y, b[5], s[5]);
    split_bf(v1.z, b[6], s[6]); split_bf(v1.w, b[7], s[7]);
    uint4 ub, us;
    ub.x = pack_bf(b[0], b[1]); ub.y = pack_bf(b[2], b[3]);
    ub.z = pack_bf(b[4], b[5]); ub.w = pack_bf(b[6], b[7]);
    us.x = pack_bf(s[0], s[1]); us.y = pack_bf(s[2], s[3]);
    us.z = pack_bf(s[4], s[5]); us.w = pack_bf(s[6], s[7]);
    *(uint4*)(db + i) = ub;
    *(uint4*)(ds + i) = us;
}

// ---------------- embedding ----------------
__global__ void embed_kernel(const int* __restrict__ idx,
                             const float* __restrict__ wte,
                             const float* __restrict__ wpe) {
    int n = blockIdx.x;
    int t = n & (Tt - 1);
    int tok = idx[n];
    const float4* src = (const float4*)(wte + (size_t)tok * Dd);
    const float4* pp  = (const float4*)(wpe + (size_t)t * Dd);
    float4* dst = (float4*)(g_x + (size_t)n * Dd);
    int i = threadIdx.x;
    float4 a = src[i], b = pp[i];
    a.x += b.x; a.y += b.y; a.z += b.z; a.w += b.w;
    dst[i] = a;
}

// ---------------- rmsnorm: bf16 planes (+optional fp32 out, +optional fused router) ----------------
// ROUTER=1: warp w computes router logit for expert w from the normalized row
// staged in smem, then thread 0 softmaxes into g_probsT.
// STOREF=1: store fp32 row only for last-position tokens (the only consumers).
template<int ROUTER, int STOREF>
__global__ void rmsnorm_kernel(const float* __restrict__ x,
                               const float* __restrict__ w,
                               float* __restrict__ o,
                               bf16* __restrict__ ob, bf16* __restrict__ os,
                               const float* __restrict__ rw) {
    int n = blockIdx.x;
    const float4* xr = (const float4*)(x + (size_t)n * Dd);
    float4 v = xr[threadIdx.x];
    float s = v.x*v.x + v.y*v.y + v.z*v.z + v.w*v.w;
    __shared__ float red[8];
    for (int off = 16; off; off >>= 1) s += __shfl_xor_sync(~0u, s, off);
    if ((threadIdx.x & 31) == 0) red[threadIdx.x >> 5] = s;
    __syncthreads();
    if (threadIdx.x < 8) {
        float t = red[threadIdx.x];
        for (int off = 4; off; off >>= 1) t += __shfl_xor_sync(0xffu, t, off);
        if (threadIdx.x == 0) red[0] = t;
    }
    __syncthreads();
    float rs = rsqrtf(red[0] * (1.0f / Dd) + 1e-6f);
    float4 wv = ((const float4*)w)[threadIdx.x];
    float4 ov;
    ov.x = v.x * rs * wv.x; ov.y = v.y * rs * wv.y;
    ov.z = v.z * rs * wv.z; ov.w = v.w * rs * wv.w;
    if (STOREF && ((n & (Tt - 1)) == Tt - 1))
        ((float4*)(o + (size_t)n * Dd))[threadIdx.x] = ov;
    bf16 b0,b1,b2,b3,s0,s1,s2,s3;
    split_bf(ov.x,b0,s0); split_bf(ov.y,b1,s1); split_bf(ov.z,b2,s2); split_bf(ov.w,b3,s3);
    bf162* pb = (bf162*)(ob + (size_t)n * Dd) + threadIdx.x * 2;
    bf162* ps = (bf162*)(os + (size_t)n * Dd) + threadIdx.x * 2;
    bf162 t;
    t.x=b0; t.y=b1; pb[0]=t;  t.x=b2; t.y=b3; pb[1]=t;
    t.x=s0; t.y=s1; ps[0]=t;  t.x=s2; t.y=s3; ps[1]=t;

    if (ROUTER) {
        __shared__ float sxn[Dd];
        __shared__ float lg[Ee];
        *(float4*)(sxn + threadIdx.x * 4) = ov;
        __syncthreads();
        int wid = threadIdx.x >> 5, lane = threadIdx.x & 31;   // 8 warps = 8 experts
        const float* we = rw + (size_t)wid * Dd;
        float acc = 0.f;
        for (int i = lane; i < Dd; i += 32) acc += sxn[i] * we[i];
        for (int off = 16; off; off >>= 1) acc += __shfl_xor_sync(~0u, acc, off);
        if (!lane) lg[wid] = acc;
        __syncthreads();
        if (threadIdx.x == 0) {
            float mx = lg[0];
            #pragma unroll
            for (int e = 1; e < Ee; e++) mx = fmaxf(mx, lg[e]);
            float p[Ee]; float sum = 0.f;
            #pragma unroll
            for (int e = 0; e < Ee; e++) { p[e] = expf(lg[e] - mx); sum += p[e]; }
            float inv = 1.f / sum;
            #pragma unroll
            for (int e = 0; e < Ee; e++) g_probsT[(size_t)e * Nn + n] = p[e] * inv;
        }
    }
}

// ---------------- 3xBF16 tensor-core GEMM: C[M,N] = A[M,K] * B[N,K]^T ----------------
// CTA tile 128x256, 8 warps of 64x64 (2x4 grid), BK=32, 3-stage cp.async pipeline.
// acc += Ab*Bb + Ab*Bs + As*Bb, term-major issue.
// OUT: 1=f32 accumulate, 3=bf16 planes (0.125 on cols<Dd), 4=gelu+bf16 planes,
//      5=atomicAdd weighted scatter. GATHER: A rows via sel[].
#define SMSH 40                          // halves per smem row (32 + 8 pad)
#define A_PL (128*SMSH)                  // A plane halves (5120)
#define B_PL (256*SMSH)                  // B plane halves (10240)
#define STG_H (2*A_PL + 2*B_PL)          // halves per stage (30720)
#define STG_B (STG_H*2)                  // bytes per stage (61440)
#define NSTG 3
#define GM_DSM (NSTG*STG_B + 512)        // 184832 B

template<int GATHER, int OUT>
__global__ void __launch_bounds__(256, 1) bf3_gemm(
    const bf16* __restrict__ Ab_, const bf16* __restrict__ As_,
    const bf16* __restrict__ Bb_, const bf16* __restrict__ Bs_,
    float* __restrict__ Cf, bf16* __restrict__ Cb, bf16* __restrict__ Cs,
    const int* __restrict__ sel, const float* __restrict__ wgt,
    int M, int N, int K, long sA, long sB, long sC) {
    extern __shared__ bf16 sh[];
    uint32_t sbase = smem_u32(sh);
    int* srow = (int*)(sh + NSTG * STG_H);

    const int tid = threadIdx.x, lane = tid & 31, warp = tid >> 5;
    const int z = blockIdx.z;
    const int bm = blockIdx.y * 128, bn = blockIdx.x * 256;
    Ab_ += (size_t)z * sA;  As_ += (size_t)z * sA;
    Bb_ += (size_t)z * sB;  Bs_ += (size_t)z * sB;
    const int* selz = sel ? sel + z * TOPK : nullptr;
    const float* wgtz = wgt ? wgt + z * TOPK : nullptr;

    if (GATHER && tid < 128) srow[tid] = selz[bm + tid];
    if (GATHER) __syncthreads();

    auto load_chunk = [&](int kc, int slot) {
        const int ko = kc * 32;
        const uint32_t stg = sbase + slot * STG_B;
        #pragma unroll 2
        for (int i = tid; i < 512; i += 256) {
            int row = i >> 2, c16 = i & 3;
            int gr = GATHER ? srow[row] : (bm + row);
            size_t off = (size_t)gr * K + ko + c16 * 8;
            uint32_t d = stg + (row * SMSH + c16 * 8) * 2;
            cpa16(d, Ab_ + off);
            cpa16(d + A_PL * 2, As_ + off);
        }
        #pragma unroll 4
        for (int i = tid; i < 1024; i += 256) {
            int row = i >> 2, c16 = i & 3;
            size_t off = (size_t)(bn + row) * K + ko + c16 * 8;
            uint32_t d = stg + 2 * A_PL * 2 + (row * SMSH + c16 * 8) * 2;
            cpa16(d, Bb_ + off);
            cpa16(d + B_PL * 2, Bs_ + off);
        }
        asm volatile("cp.async.commit_group;");
    };

    const int wm = warp & 1, wn = warp >> 1;          // 2 x 4 warp grid, 64x64 tiles
    const int arow = (lane & 7) + ((lane >> 3) & 1) * 8;
    const int acol = (lane >> 4) * 8;
    const int brow = (lane & 7) + ((lane >> 4) & 1) * 8;
    const int bcol = ((lane >> 3) & 1) * 8;

    float acc[4][8][4];
    #pragma unroll
    for (int i = 0; i < 4; i++)
        #pragma unroll
        for (int j = 0; j < 8; j++)
            #pragma unroll
            for (int q = 0; q < 4; q++) acc[i][j][q] = 0.f;

    const int NC = K >> 5;
    load_chunk(0, 0);
    load_chunk(1, 1);

    for (int c = 0; c < NC; c++) {
        if (c + 2 < NC) {
            load_chunk(c + 2, (c + 2) % NSTG);
            asm volatile("cp.async.wait_group 2;");
        } else if (c + 1 < NC) {
            asm volatile("cp.async.wait_group 1;");
        } else {
            asm volatile("cp.async.wait_group 0;");
        }
        __syncthreads();

        const uint32_t stg = sbase + (c % NSTG) * STG_B;
        #pragma unroll
        for (int ks = 0; ks < 2; ks++) {
            uint32_t bb[4][4], bs2[4][4], ab[4][4], as2[4][4];
            #pragma unroll
            for (int t16 = 0; t16 < 4; t16++) {
                uint32_t ad = stg + 2 * A_PL * 2 +
                              ((wn * 64 + t16 * 16 + brow) * SMSH + ks * 16 + bcol) * 2;
                ldsm4(bb[t16],  ad);
                ldsm4(bs2[t16], ad + B_PL * 2);
            }
            #pragma unroll
            for (int mf = 0; mf < 4; mf++) {
                uint32_t ad = stg + ((wm * 64 + mf * 16 + arow) * SMSH + ks * 16 + acol) * 2;
                ldsm4(ab[mf],  ad);
                ldsm4(as2[mf], ad + A_PL * 2);
            }
            #pragma unroll
            for (int mf = 0; mf < 4; mf++)
                #pragma unroll
                for (int nf = 0; nf < 8; nf++) {
                    int p = nf >> 1, e = (nf & 1) * 2;
                    mma_bf16(acc[mf][nf], ab[mf], bb[p][e], bb[p][e + 1]);
                }
            #pragma unroll
            for (int mf = 0; mf < 4; mf++)
                #pragma unroll
                for (int nf = 0; nf < 8; nf++) {
                    int p = nf >> 1, e = (nf & 1) * 2;
                    mma_bf16(acc[mf][nf], ab[mf], bs2[p][e], bs2[p][e + 1]);
                }
            #pragma unroll
            for (int mf = 0; mf < 4; mf++)
                #pragma unroll
                for (int nf = 0; nf < 8; nf++) {
                    int p = nf >> 1, e = (nf & 1) * 2;
                    mma_bf16(acc[mf][nf], as2[mf], bb[p][e], bb[p][e + 1]);
                }
        }
        __syncthreads();
    }

    // epilogue
    const int cr = lane >> 2, cc = (lane & 3) * 2;
    #pragma unroll
    for (int mf = 0; mf < 4; mf++) {
        int rk0 = bm + wm * 64 + mf * 16 + cr;
        int tok0 = 0, tok1 = 0; float w0 = 0.f, w1 = 0.f;
        if (OUT == 5) {
            tok0 = selz[rk0]; tok1 = selz[rk0 + 8];
            w0 = wgtz[rk0];   w1 = wgtz[rk0 + 8];
        }
        #pragma unroll
        for (int nf = 0; nf < 8; nf++) {
            int col  = bn + wn * 64 + nf * 8 + cc;
            float c0 = acc[mf][nf][0], c1 = acc[mf][nf][1];
            float c2 = acc[mf][nf][2], c3 = acc[mf][nf][3];
            if (OUT == 4) { c0 = gelu_f(c0); c1 = gelu_f(c1); c2 = gelu_f(c2); c3 = gelu_f(c3); }
            if (OUT == 3) {
                float sc = (col < Dd) ? 0.125f : 1.f;
                c0 *= sc; c1 *= sc; c2 *= sc; c3 *= sc;
            }
            if (OUT == 3 || OUT == 4) {
                size_t o0 = (size_t)z * sC + (size_t)rk0 * N + col;
                size_t o1 = o0 + (size_t)8 * N;
                bf16 b0,b1,b2,b3,s0,s1,s2,s3;
                split_bf(c0,b0,s0); split_bf(c1,b1,s1);
                split_bf(c2,b2,s2); split_bf(c3,b3,s3);
                bf162 t;
                t.x=b0; t.y=b1; *(bf162*)(Cb + o0) = t;
                t.x=b2; t.y=b3; *(bf162*)(Cb + o1) = t;
                t.x=s0; t.y=s1; *(bf162*)(Cs + o0) = t;
                t.x=s2; t.y=s3; *(bf162*)(Cs + o1) = t;
            } else if (OUT == 5) {
                float* d0 = Cf + (size_t)tok0 * N + col;
                float* d1 = Cf + (size_t)tok1 * N + col;
                atomicAdd(d0,     w0 * c0); atomicAdd(d0 + 1, w0 * c1);
                atomicAdd(d1,     w1 * c2); atomicAdd(d1 + 1, w1 * c3);
            } else {
                float* p0 = Cf + (size_t)z * sC + (size_t)rk0 * N + col;
                float* p1 = p0 + (size_t)8 * N;
                p0[0] += c0; p0[1] += c1;
                p1[0] += c2; p1[1] += c3;
            }
        }
    }
}

// ---------------- tensor-core flash attention (causal, HD=64, BQ=BK=64) ----------------
// 4 warps, each owns 16 Q rows. 3xBF16 split; K/V double-buffered; 2 CTAs/SM.
#define FH 72                       // smem stride in halves
#define FPL (64*FH*2)               // plane bytes (9216)
#define FS2 (10*FPL)                // Q(2) + 2 stages of K/V(4 each) = 92160
__global__ void __launch_bounds__(128, 2) flashm_kernel() {
    extern __shared__ bf16 fsh[];
    uint32_t sb = smem_u32(fsh);
    int qt = blockIdx.x, bh = blockIdx.y;
    int b = bh >> 4, h = bh & 15;
    int tid = threadIdx.x, lane = tid & 31, warp = tid >> 5;

    for (int i = tid; i < 512; i += 128) {
        int row = i >> 3, cc = i & 7;
        size_t g = ((size_t)(b * Tt + qt * 64 + row)) * (3 * Dd) + h * HDc + cc * 8;
        uint32_t ds = (row * FH + cc * 8) * 2;
        cpa16(sb + ds,       g_qkv_b + g);
        cpa16(sb + FPL + ds, g_qkv_s + g);
    }
    asm volatile("cp.async.commit_group;");

    auto load_kv = [&](int kt, int s) {
        uint32_t base = sb + (2 + 4 * s) * FPL;
        for (int i = tid; i < 512; i += 128) {
            int row = i >> 3, cc = i & 7;
            size_t gk = ((size_t)(b * Tt + kt * 64 + row)) * (3 * Dd) + Dd + h * HDc + cc * 8;
            size_t gv = gk + Dd;
            uint32_t ds = (row * FH + cc * 8) * 2;
            cpa16(base + ds,           g_qkv_b + gk);
            cpa16(base + FPL + ds,     g_qkv_s + gk);
            cpa16(base + 2 * FPL + ds, g_qkv_b + gv);
            cpa16(base + 3 * FPL + ds, g_qkv_s + gv);
        }
        asm volatile("cp.async.commit_group;");
    };

    load_kv(0, 0);
    asm volatile("cp.async.wait_group 1;");
    __syncthreads();

    uint32_t qb[4][4], qs[4][4];
    {
        int row = warp * 16 + (lane & 15);
        #pragma unroll
        for (int kc = 0; kc < 4; kc++) {
            int col = kc * 16 + (lane >> 4) * 8;
            uint32_t ad = (row * FH + col) * 2;
            ldsm4(qb[kc], sb + ad);
            ldsm4(qs[kc], sb + FPL + ad);
        }
    }

    float Oacc[8][4];
    #pragma unroll
    for (int i = 0; i < 8; i++)
        #pragma unroll
        for (int q = 0; q < 4; q++) Oacc[i][q] = 0.f;
    float mrun[2] = {-1e30f, -1e30f}, lrun[2] = {0.f, 0.f};

    const int qrowA = qt * 64 + warp * 16 + (lane >> 2);

    for (int kt = 0; kt <= qt; kt++) {
        if (kt + 1 <= qt) {
            load_kv(kt + 1, (kt + 1) & 1);
            asm volatile("cp.async.wait_group 1;");
        } else {
            asm volatile("cp.async.wait_group 0;");
        }
        __syncthreads();
        uint32_t kvb = sb + (2 + 4 * (kt & 1)) * FPL;

        float S[8][4];
        #pragma unroll
        for (int i = 0; i < 8; i++)
            #pragma unroll
            for (int q = 0; q < 4; q++) S[i][q] = 0.f;
        #pragma unroll
        for (int kc = 0; kc < 4; kc++) {
            int c = kc * 16 + (lane >> 4) * 8;
            #pragma unroll
            for (int g2 = 0; g2 < 4; g2++) {
                uint32_t kbF[4], ksF[4];
                uint32_t ad = ((g2 * 16 + (lane & 15)) * FH + c) * 2;
                ldsm4(kbF, kvb + ad);
                ldsm4(ksF, kvb + FPL + ad);
                mma_bf16(S[2*g2],   qb[kc], kbF[0], kbF[2]);
                mma_bf16(S[2*g2+1], qb[kc], kbF[1], kbF[3]);
                mma_bf16(S[2*g2],   qb[kc], ksF[0], ksF[2]);
                mma_bf16(S[2*g2+1], qb[kc], ksF[1], ksF[3]);
                mma_bf16(S[2*g2],   qs[kc], kbF[0], kbF[2]);
                mma_bf16(S[2*g2+1], qs[kc], kbF[1], kbF[3]);
            }
        }

        if (kt == qt) {
            #pragma unroll
            for (int nt = 0; nt < 8; nt++) {
                int t0 = kt * 64 + nt * 8 + (lane & 3) * 2;
                if (t0     > qrowA)     S[nt][0] = -1e30f;
                if (t0 + 1 > qrowA)     S[nt][1] = -1e30f;
                if (t0     > qrowA + 8) S[nt][2] = -1e30f;
                if (t0 + 1 > qrowA + 8) S[nt][3] = -1e30f;
            }
        }

        float mA = -1e30f, mB = -1e30f;
        #pragma unroll
        for (int nt = 0; nt < 8; nt++) {
            mA = fmaxf(mA, fmaxf(S[nt][0], S[nt][1]));
            mB = fmaxf(mB, fmaxf(S[nt][2], S[nt][3]));
        }
        mA = fmaxf(mA, __shfl_xor_sync(~0u, mA, 1));
        mA = fmaxf(mA, __shfl_xor_sync(~0u, mA, 2));
        mB = fmaxf(mB, __shfl_xor_sync(~0u, mB, 1));
        mB = fmaxf(mB, __shfl_xor_sync(~0u, mB, 2));
        float mnA = fmaxf(mrun[0], mA), mnB = fmaxf(mrun[1], mB);
        float aA = expf(mrun[0] - mnA), aB = expf(mrun[1] - mnB);
        float sumA = 0.f, sumB = 0.f;
        uint32_t Pb[4][4], Ps[4][4];
        #pragma unroll
        for (int tc = 0; tc < 4; tc++) {
            #pragma unroll
            for (int hf = 0; hf < 2; hf++) {
                int nt = tc * 2 + hf;
                float p0 = expf(S[nt][0] - mnA), p1 = expf(S[nt][1] - mnA);
                float p2 = expf(S[nt][2] - mnB), p3 = expf(S[nt][3] - mnB);
                sumA += p0 + p1; sumB += p2 + p3;
                bf16 b0,b1,b2,b3,s0,s1,s2,s3;
                split_bf(p0,b0,s0); split_bf(p1,b1,s1);
                split_bf(p2,b2,s2); split_bf(p3,b3,s3);
                Pb[tc][hf*2+0] = pack_bf(b0, b1);
                Pb[tc][hf*2+1] = pack_bf(b2, b3);
                Ps[tc][hf*2+0] = pack_bf(s0, s1);
                Ps[tc][hf*2+1] = pack_bf(s2, s3);
            }
        }
        sumA += __shfl_xor_sync(~0u, sumA, 1);
        sumA += __shfl_xor_sync(~0u, sumA, 2);
        sumB += __shfl_xor_sync(~0u, sumB, 1);
        sumB += __shfl_xor_sync(~0u, sumB, 2);
        lrun[0] = lrun[0] * aA + sumA;  mrun[0] = mnA;
        lrun[1] = lrun[1] * aB + sumB;  mrun[1] = mnB;
        #pragma unroll
        for (int nt = 0; nt < 8; nt++) {
            Oacc[nt][0] *= aA; Oacc[nt][1] *= aA;
            Oacc[nt][2] *= aB; Oacc[nt][3] *= aB;
        }

        #pragma unroll
        for (int tc = 0; tc < 4; tc++) {
            int r = tc * 16 + (lane & 15);
            #pragma unroll
            for (int dg = 0; dg < 4; dg++) {
                int c = dg * 16 + (lane >> 4) * 8;
                uint32_t vbF[4], vsF[4];
                uint32_t ad = (r * FH + c) * 2;
                ldsm4t(vbF, kvb + 2 * FPL + ad);
                ldsm4t(vsF, kvb + 3 * FPL + ad);
                mma_bf16(Oacc[2*dg],   Pb[tc], vbF[0], vbF[1]);
                mma_bf16(Oacc[2*dg+1], Pb[tc], vbF[2], vbF[3]);
                mma_bf16(Oacc[2*dg],   Pb[tc], vsF[0], vsF[1]);
                mma_bf16(Oacc[2*dg+1], Pb[tc], vsF[2], vsF[3]);
                mma_bf16(Oacc[2*dg],   Ps[tc], vbF[0], vbF[1]);
                mma_bf16(Oacc[2*dg+1], Ps[tc], vbF[2], vbF[3]);
            }
        }
        __syncthreads();
    }

    float liA = 1.f / lrun[0], liB = 1.f / lrun[1];
    size_t rowA = (size_t)(b * Tt + qt * 64 + warp * 16 + (lane >> 2)) * Dd;
    size_t rowB = rowA + (size_t)8 * Dd;
    #pragma unroll
    for (int nt = 0; nt < 8; nt++) {
        int col = h * HDc + nt * 8 + (lane & 3) * 2;
        float v0 = Oacc[nt][0] * liA, v1 = Oacc[nt][1] * liA;
        float v2 = Oacc[nt][2] * liB, v3 = Oacc[nt][3] * liB;
        bf16 b0,b1,b2,b3,s0,s1,s2,s3;
        split_bf(v0,b0,s0); split_bf(v1,b1,s1);
        split_bf(v2,b2,s2); split_bf(v3,b3,s3);
        bf162 t;
        t.x=b0; t.y=b1; *(bf162*)(g_y_b + rowA + col) = t;
        t.x=b2; t.y=b3; *(bf162*)(g_y_b + rowB + col) = t;
        t.x=s0; t.y=s1; *(bf162*)(g_y_s + rowA + col) = t;
        t.x=s2; t.y=s3; *(bf162*)(g_y_s + rowB + col) = t;
    }
}

// ---------------- per-expert top-1024 of 4096 via in-smem bitonic sort ----------------
__global__ void __launch_bounds__(1024) topk_kernel() {
    int e = blockIdx.x;
    __shared__ float key[4096];
    __shared__ int   val[4096];
    for (int i = threadIdx.x; i < 4096; i += 1024) {
        key[i] = g_probsT[(size_t)e * Nn + i];
        val[i] = i;
    }
    __syncthreads();
    for (int k = 2; k <= 4096; k <<= 1) {
        for (int j = k >> 1; j > 0; j >>= 1) {
            for (int i = threadIdx.x; i < 4096; i += 1024) {
                int ixj = i ^ j;
                if (ixj > i) {
                    bool dirDesc = ((i & k) == 0);
                    float ka = key[i], kb = key[ixj];
                    int va = val[i], vb = val[ixj];
                    bool aFirst = (ka > kb) || (ka == kb && va < vb);
                    if (dirDesc ? !aFirst : aFirst) {
                        key[i] = kb; key[ixj] = ka;
                        val[i] = vb; val[ixj] = va;
                    }
                }
            }
            __syncthreads();
        }
    }
    if (threadIdx.x < TOPK) {
        g_sel[e * TOPK + threadIdx.x] = val[threadIdx.x];
        g_wgt[e * TOPK + threadIdx.x] = key[threadIdx.x];
    }
}

// ---------------- last-layer MoE fast path ----------------
// rank-count: last-pos token of batch b is in expert e's top-1024 iff
// #{t: p[t] > p[target]} + #{t < target: p[t] == p[target]} < TOPK.
__global__ void __launch_bounds__(1024) moe_rank_kernel() {
    int e = blockIdx.x >> 2, b = blockIdx.x & 3;
    int target = b * Tt + (Tt - 1);
    const float* pr = g_probsT + (size_t)e * Nn;
    float pt = pr[target];
    int cnt = 0;
    for (int i = threadIdx.x; i < Nn; i += 1024) {
        float v = pr[i];
        if (v > pt || (v == pt && i < target)) cnt++;
    }
    for (int off = 16; off; off >>= 1) cnt += __shfl_xor_sync(~0u, cnt, off);
    __shared__ int red[32];
    if ((threadIdx.x & 31) == 0) red[threadIdx.x >> 5] = cnt;
    __syncthreads();
    if (threadIdx.x < 32) {
        int t = red[threadIdx.x];
        for (int off = 16; off; off >>= 1) t += __shfl_xor_sync(~0u, t, off);
        if (threadIdx.x == 0) {
            g_lpk[blockIdx.x] = (t < TOPK) ? 0 : -1;
            g_lpw[blockIdx.x] = pt;
        }
    }
}

__global__ void __launch_bounds__(256) moe_fcvec_kernel(const float* __restrict__ fcw) {
    int e = blockIdx.x;
    __shared__ float sx[Bb][Dd];
    __shared__ int act[Bb];
    if (threadIdx.x < Bb) act[threadIdx.x] = g_lpk[e * Bb + threadIdx.x];
    __syncthreads();
    if (act[0] < 0 && act[1] < 0 && act[2] < 0 && act[3] < 0) return;
    #pragma unroll
    for (int b = 0; b < Bb; b++) {
        const float* xr = g_xn + ((size_t)(b * Tt + Tt - 1)) * Dd;
        for (int i = threadIdx.x; i < Dd; i += 256)
            sx[b][i] = (act[b] >= 0) ? xr[i] : 0.f;
    }
    __syncthreads();
    int warp = threadIdx.x >> 5, lane = threadIdx.x & 31;
    for (int j = 0; j < 32; j++) {
        int f = blockIdx.y * 256 + warp * 32 + j;
        const float* wr = fcw + ((size_t)e * DFFc + f) * Dd;
        float a0 = 0.f, a1 = 0.f, a2 = 0.f, a3 = 0.f;
        for (int i = lane; i < Dd; i += 32) {
            float wv = wr[i];
            a0 += wv * sx[0][i]; a1 += wv * sx[1][i];
            a2 += wv * sx[2][i]; a3 += wv * sx[3][i];
        }
        for (int off = 16; off; off >>= 1) {
            a0 += __shfl_xor_sync(~0u, a0, off);
            a1 += __shfl_xor_sync(~0u, a1, off);
            a2 += __shfl_xor_sync(~0u, a2, off);
            a3 += __shfl_xor_sync(~0u, a3, off);
        }
        if (!lane) {
            if (act[0] >= 0) g_hv[((size_t)e * Bb + 0) * DFFc + f] = gelu_f(a0);
            if (act[1] >= 0) g_hv[((size_t)e * Bb + 1) * DFFc + f] = gelu_f(a1);
            if (act[2] >= 0) g_hv[((size_t)e * Bb + 2) * DFFc + f] = gelu_f(a2);
            if (act[3] >= 0) g_hv[((size_t)e * Bb + 3) * DFFc + f] = gelu_f(a3);
        }
    }
}

__global__ void __launch_bounds__(256) moe_mpvec_kernel(const float* __restrict__ mpw) {
    extern __shared__ float shv[];
    int e = blockIdx.x;
    __shared__ int act[Bb];
    __shared__ float awt[Bb];
    if (threadIdx.x < Bb) {
        act[threadIdx.x] = g_lpk[e * Bb + threadIdx.x];
        awt[threadIdx.x] = g_lpw[e * Bb + threadIdx.x];
    }
    __syncthreads();
    if (act[0] < 0 && act[1] < 0 && act[2] < 0 && act[3] < 0) return;
    #pragma unroll
    for (int b = 0; b < Bb; b++) {
        const float* hr = g_hv + ((size_t)e * Bb + b) * DFFc;
        for (int i = threadIdx.x; i < DFFc; i += 256)
            shv[b * DFFc + i] = (act[b] >= 0) ? hr[i] : 0.f;
    }
    __syncthreads();
    int warp = threadIdx.x >> 5, lane = threadIdx.x & 31;
    for (int j = 0; j < 32; j++) {
        int d = blockIdx.y * 256 + warp * 32 + j;
        const float* wr = mpw + ((size_t)e * Dd + d) * DFFc;
        float a0 = 0.f, a1 = 0.f, a2 = 0.f, a3 = 0.f;
        for (int i = lane; i < DFFc; i += 32) {
            float wv = wr[i];
            a0 += wv * shv[i]; a1 += wv * shv[DFFc + i];
            a2 += wv * shv[2 * DFFc + i]; a3 += wv * shv[3 * DFFc + i];
        }
        for (int off = 16; off; off >>= 1) {
            a0 += __shfl_xor_sync(~0u, a0, off);
            a1 += __shfl_xor_sync(~0u, a1, off);
            a2 += __shfl_xor_sync(~0u, a2, off);
            a3 += __shfl_xor_sync(~0u, a3, off);
        }
        if (!lane) {
            if (act[0] >= 0) atomicAdd(&g_x[((size_t)(0 * Tt + Tt - 1)) * Dd + d], awt[0] * a0);
            if (act[1] >= 0) atomicAdd(&g_x[((size_t)(1 * Tt + Tt - 1)) * Dd + d], awt[1] * a1);
            if (act[2] >= 0) atomicAdd(&g_x[((size_t)(2 * Tt + Tt - 1)) * Dd + d], awt[2] * a2);
            if (act[3] >= 0) atomicAdd(&g_x[((size_t)(3 * Tt + Tt - 1)) * Dd + d], awt[3] * a3);
        }
    }
}

// ---------------- final rmsnorm (last position of each batch only) ----------------
__global__ void lnf_kernel(const float* __restrict__ w) {
    int b = blockIdx.x;
    const float4* xr = (const float4*)(g_x + ((size_t)b * Tt + (Tt - 1)) * Dd);
    float4 v = xr[threadIdx.x];
    float s = v.x*v.x + v.y*v.y + v.z*v.z + v.w*v.w;
    __shared__ float red[8];
    for (int off = 16; off; off >>= 1) s += __shfl_xor_sync(~0u, s, off);
    if ((threadIdx.x & 31) == 0) red[threadIdx.x >> 5] = s;
    __syncthreads();
    if (threadIdx.x < 8) {
        float t = red[threadIdx.x];
        for (int off = 4; off; off >>= 1) t += __shfl_xor_sync(0xffu, t, off);
        if (threadIdx.x == 0) red[0] = t;
    }
    __syncthreads();
    float rs = rsqrtf(red[0] * (1.0f / Dd) + 1e-6f);
    float4 wv = ((const float4*)w)[threadIdx.x];
    float4 ov;
    ov.x = v.x * rs * wv.x; ov.y = v.y * rs * wv.y;
    ov.z = v.z * rs * wv.z; ov.w = v.w * rs * wv.w;
    ((float4*)(g_xf + (size_t)b * Dd))[threadIdx.x] = ov;
}

// ---------------- LM head: logits[b][v] = dot(xf[b], wte[v]) ----------------
__global__ void __launch_bounds__(256) lmhead_kernel(const float* __restrict__ wte,
                                                     float* __restrict__ out) {
    __shared__ float4 sx[4 * 256];
    for (int i = threadIdx.x; i < 1024; i += 256) sx[i] = ((const float4*)g_xf)[i];
    __syncthreads();
    int w = threadIdx.x >> 5, lane = threadIdx.x & 31;
    int v = blockIdx.x * 8 + w;
    if (v >= Vv) return;
    const float4* wr = (const float4*)(wte + (size_t)v * Dd);
    float a0 = 0.f, a1 = 0.f, a2 = 0.f, a3 = 0.f;
    for (int i = lane; i < 256; i += 32) {
        float4 t = wr[i];
        float4 x0 = sx[i], x1 = sx[256 + i], x2 = sx[512 + i], x3 = sx[768 + i];
        a0 += t.x*x0.x + t.y*x0.y + t.z*x0.z + t.w*x0.w;
        a1 += t.x*x1.x + t.y*x1.y + t.z*x1.z + t.w*x1.w;
        a2 += t.x*x2.x + t.y*x2.y + t.z*x2.z + t.w*x2.w;
        a3 += t.x*x3.x + t.y*x3.y + t.z*x3.z + t.w*x3.w;
    }
    for (int off = 16; off; off >>= 1) {
        a0 += __shfl_xor_sync(~0u, a0, off);
        a1 += __shfl_xor_sync(~0u, a1, off);
        a2 += __shfl_xor_sync(~0u, a2, off);
        a3 += __shfl_xor_sync(~0u, a3, off);
    }
    if (!lane) {
        out[v]          = a0;
        out[Vv + v]     = a1;
        out[2 * Vv + v] = a2;
        out[3 * Vv + v] = a3;
    }
}

// ---------------- host orchestration ----------------
extern "C" void kernel_launch(void* const* d_in, const int* in_sizes, int n_in,
                              void* d_out, int out_size) {
    const int*   idx  = (const int*)  d_in[0];
    const float* wte  = (const float*)d_in[1];
    const float* wpe  = (const float*)d_in[2];
    const float* ln1  = (const float*)d_in[3];
    const float* attw = (const float*)d_in[4];
    const float* prjw = (const float*)d_in[5];
    const float* ln2  = (const float*)d_in[6];
    const float* rw   = (const float*)d_in[7];
    const float* fcw  = (const float*)d_in[8];
    const float* mpw  = (const float*)d_in[9];
    const float* lnf  = (const float*)d_in[10];
    float* out = (float*)d_out;

    void* p;
    cudaGetSymbolAddress(&p, g_x);     float* x    = (float*)p;
    cudaGetSymbolAddress(&p, g_xn);    float* xn   = (float*)p;
    cudaGetSymbolAddress(&p, g_sel);   int*   sel  = (int*)p;
    cudaGetSymbolAddress(&p, g_wgt);   float* wgt  = (float*)p;
    cudaGetSymbolAddress(&p, g_xn_b);  bf16* xn_b  = (bf16*)p;
    cudaGetSymbolAddress(&p, g_xn_s);  bf16* xn_s  = (bf16*)p;
    cudaGetSymbolAddress(&p, g_qkv_b); bf16* qkv_b = (bf16*)p;
    cudaGetSymbolAddress(&p, g_qkv_s); bf16* qkv_s = (bf16*)p;
    cudaGetSymbolAddress(&p, g_y_b);   bf16* y_b   = (bf16*)p;
    cudaGetSymbolAddress(&p, g_y_s);   bf16* y_s   = (bf16*)p;
    cudaGetSymbolAddress(&p, g_h_b);   bf16* h_b   = (bf16*)p;
    cudaGetSymbolAddress(&p, g_h_s);   bf16* h_s   = (bf16*)p;
    cudaGetSymbolAddress(&p, g_attw_b);bf16* attw_b= (bf16*)p;
    cudaGetSymbolAddress(&p, g_attw_s);bf16* attw_s= (bf16*)p;
    cudaGetSymbolAddress(&p, g_prjw_b);bf16* prjw_b= (bf16*)p;
    cudaGetSymbolAddress(&p, g_prjw_s);bf16* prjw_s= (bf16*)p;
    cudaGetSymbolAddress(&p, g_fcw_b); bf16* fcw_b = (bf16*)p;
    cudaGetSymbolAddress(&p, g_fcw_s); bf16* fcw_s = (bf16*)p;
    cudaGetSymbolAddress(&p, g_mpw_b); bf16* mpw_b = (bf16*)p;
    cudaGetSymbolAddress(&p, g_mpw_s); bf16* mpw_s = (bf16*)p;

    cudaFuncSetAttribute(flashm_kernel, cudaFuncAttributeMaxDynamicSharedMemorySize, FS2);
    cudaFuncSetAttribute(bf3_gemm<0,3>, cudaFuncAttributeMaxDynamicSharedMemorySize, GM_DSM);
    cudaFuncSetAttribute(bf3_gemm<0,1>, cudaFuncAttributeMaxDynamicSharedMemorySize, GM_DSM);
    cudaFuncSetAttribute(bf3_gemm<1,4>, cudaFuncAttributeMaxDynamicSharedMemorySize, GM_DSM);
    cudaFuncSetAttribute(bf3_gemm<0,5>, cudaFuncAttributeMaxDynamicSharedMemorySize, GM_DSM);
    cudaFuncSetAttribute(moe_mpvec_kernel, cudaFuncAttributeMaxDynamicSharedMemorySize, Bb * DFFc * 4);

    // weight split conversion (once per call); fc/mp only needed for layer 0
    wconvert_kernel<<<(Ll*3*Dd*Dd)/2048, 256>>>(attw, attw_b, attw_s, Ll*3*Dd*Dd);
    wconvert_kernel<<<(Ll*Dd*Dd)/2048, 256>>>(prjw, prjw_b, prjw_s, Ll*Dd*Dd);
    wconvert_kernel<<<(Ee*DFFc*Dd)/2048, 256>>>(fcw, fcw_b, fcw_s, Ee*DFFc*Dd);
    wconvert_kernel<<<(Ee*Dd*DFFc)/2048, 256>>>(mpw, mpw_b, mpw_s, Ee*Dd*DFFc);

    embed_kernel<<<Nn, 256>>>(idx, wte, wpe);

    for (int l = 0; l < Ll; l++) {
        // attention block
        rmsnorm_kernel<0,0><<<Nn, 256>>>(x, ln1 + (size_t)l * Dd, nullptr, xn_b, xn_s, nullptr);
        bf3_gemm<0,3><<<dim3(3*Dd/256, Nn/128, 1), 256, GM_DSM>>>(
            xn_b, xn_s,
            attw_b + (size_t)l * 3 * Dd * Dd, attw_s + (size_t)l * 3 * Dd * Dd,
            nullptr, qkv_b, qkv_s, nullptr, nullptr,
            Nn, 3*Dd, Dd, 0, 0, 0);
        flashm_kernel<<<dim3(Tt/64, Bb*Hh), 128, FS2>>>();
        bf3_gemm<0,1><<<dim3(Dd/256, Nn/128, 1), 256, GM_DSM>>>(
            y_b, y_s,
            prjw_b + (size_t)l * Dd * Dd, prjw_s + (size_t)l * Dd * Dd,
            x, nullptr, nullptr, nullptr, nullptr,
            Nn, Dd, Dd, 0, 0, 0);                       // x += proj(y)

        // MoE block (router fused into rmsnorm2)
        if (l < Ll - 1) {
            rmsnorm_kernel<1,0><<<Nn, 256>>>(x, ln2 + (size_t)l * Dd, nullptr, xn_b, xn_s,
                                             rw + (size_t)l * Ee * Dd);
            topk_kernel<<<Ee, 1024>>>();
            bf3_gemm<1,4><<<dim3(DFFc/256, TOPK/128, Ee), 256, GM_DSM>>>(
                xn_b, xn_s,
                fcw_b, fcw_s,
                nullptr, h_b, h_s, sel, wgt,
                TOPK, DFFc, Dd,
                0, (long)DFFc * Dd, (long)TOPK * DFFc);
            bf3_gemm<0,5><<<dim3(Dd/256, TOPK/128, Ee), 256, GM_DSM>>>(
                h_b, h_s,
                mpw_b, mpw_s,
                x, nullptr, nullptr, sel, wgt,
                TOPK, Dd, DFFc,
                (long)TOPK * DFFc, (long)Dd * DFFc, 0); // x += w * expert_out (atomic)
        } else {
            // last layer: only the 4 last-position tokens affect the output.
            rmsnorm_kernel<1,1><<<Nn, 256>>>(x, ln2 + (size_t)l * Dd, xn, xn_b, xn_s,
                                             rw + (size_t)l * Ee * Dd);
            moe_rank_kernel<<<Ee * Bb, 1024>>>();
            moe_fcvec_kernel<<<dim3(Ee, DFFc/256), 256>>>(fcw + (size_t)l * Ee * DFFc * Dd);
            moe_mpvec_kernel<<<dim3(Ee, Dd/256), 256, Bb * DFFc * 4>>>(mpw + (size_t)l * Ee * Dd * DFFc);
        }
    }

    lnf_kernel<<<Bb, 256>>>(lnf);
    lmhead_kernel<<<(Vv + 7) / 8, 256>>>(wte, out);
}